// round 4
// baseline (speedup 1.0000x reference)
#include <cuda_runtime.h>
#include <math.h>

#define NN   100000
#define EE   300000
#define DINF 128
#define HH   512
#define GG   4096
#define OUTC 256
#define SLOPE 0.01f
#define EPS   1e-5f

// -------- scratch (device globals: allocation-free, 256B aligned) --------
__device__ __align__(256) float    g_deg[NN];
__device__ __align__(256) float    g_dinv[NN];
__device__ __align__(256) float    g_selfc[NN];
__device__ __align__(256) float    g_norm[EE];
__device__ __align__(256) float    g_buf1[(size_t)NN * HH];
__device__ __align__(256) float    g_buf2[(size_t)NN * HH];
__device__ __align__(256) float    g_buf3[(size_t)NN * HH];
__device__ __align__(256) unsigned g_keys[(size_t)GG * HH];
__device__ __align__(256) float    g_pooled[(size_t)GG * HH];
__device__ __align__(256) float    g_stats[4 * HH];
__device__ __align__(256) float    g_bna[HH];
__device__ __align__(256) float    g_bnc[HH];

// -------- init --------
__global__ void init_kernel() {
    int i = blockIdx.x * blockDim.x + threadIdx.x;
    if (i < NN) g_deg[i] = 2.0f;
    if (i < GG * HH) g_keys[i] = 0u;
    if (i < 4 * HH) g_stats[i] = 0.0f;
}

__global__ void count_deg_kernel(const int* __restrict__ ecol) {
    int e = blockIdx.x * blockDim.x + threadIdx.x;
    if (e < EE) atomicAdd(&g_deg[ecol[e]], 1.0f);
}

__global__ void dinv_kernel() {
    int i = blockIdx.x * blockDim.x + threadIdx.x;
    if (i < NN) {
        float d = g_deg[i];
        float di = rsqrtf(d);
        g_dinv[i] = di;
        g_selfc[i] = 2.0f * di * di;
    }
}

__global__ void edge_norm_kernel(const int* __restrict__ erow,
                                 const int* __restrict__ ecol) {
    int e = blockIdx.x * blockDim.x + threadIdx.x;
    if (e < EE) g_norm[e] = g_dinv[erow[e]] * g_dinv[ecol[e]];
}

// -------- packed-f32x2 SGEMM: C = A@B (+bias); optional out2 = bias2 + selfc[r]*C --------
#define BM 128
#define BN 128
#define BK 16
#define BPAD 4

__global__ __launch_bounds__(256, 2)
void sgemm_f32x2(const float* __restrict__ A, const float* __restrict__ B,
                 const float* __restrict__ bias, float* __restrict__ C,
                 const float* __restrict__ selfc, const float* __restrict__ bias2,
                 float* __restrict__ out2,
                 int M, int N, int K) {
    __shared__ float As[BK][BM];
    __shared__ float Bs[BK][BN + BPAD];
    int tid = threadIdx.x;
    int bm = blockIdx.y * BM;
    int bn = blockIdx.x * BN;
    int tcol = tid & 15;      // 16 across N; cols tcol*4..+3 and 64+tcol*4..+3
    int trow = tid >> 4;      // 16 down M; rows trow*8..+7

    unsigned long long acc2[8][4];
#pragma unroll
    for (int i = 0; i < 8; i++)
#pragma unroll
        for (int j = 0; j < 4; j++) acc2[i][j] = 0ull;

    // loaders
    int ar = tid >> 1;             // 0..127
    int ak = (tid & 1) * 8;        // 0 or 8
    int bk = tid >> 4;             // 0..15
    int bc = (tid & 15) * 8;       // 0..120

    for (int k0 = 0; k0 < K; k0 += BK) {
        // A tile: [BM][BK] transposed into As[k][row]
        float4 a0, a1;
        if (bm + ar < M) {
            const float* ap = A + (long long)(bm + ar) * K + k0 + ak;
            a0 = *reinterpret_cast<const float4*>(ap);
            a1 = *reinterpret_cast<const float4*>(ap + 4);
        } else {
            a0 = make_float4(0.f, 0.f, 0.f, 0.f);
            a1 = a0;
        }
        As[ak + 0][ar] = a0.x; As[ak + 1][ar] = a0.y;
        As[ak + 2][ar] = a0.z; As[ak + 3][ar] = a0.w;
        As[ak + 4][ar] = a1.x; As[ak + 5][ar] = a1.y;
        As[ak + 6][ar] = a1.z; As[ak + 7][ar] = a1.w;

        // B tile: rows k0+bk, cols bn+bc..+7
        {
            const float* bp = B + (long long)(k0 + bk) * N + bn + bc;
            float4 b0 = *reinterpret_cast<const float4*>(bp);
            float4 b1 = *reinterpret_cast<const float4*>(bp + 4);
            *reinterpret_cast<float4*>(&Bs[bk][bc]) = b0;
            *reinterpret_cast<float4*>(&Bs[bk][bc + 4]) = b1;
        }
        __syncthreads();

#pragma unroll
        for (int k = 0; k < BK; k++) {
            ulonglong2 bb0 = *reinterpret_cast<const ulonglong2*>(&Bs[k][tcol * 4]);
            ulonglong2 bb1 = *reinterpret_cast<const ulonglong2*>(&Bs[k][64 + tcol * 4]);
#pragma unroll
            for (int i = 0; i < 8; i++) {
                unsigned avu = __float_as_uint(As[k][trow * 8 + i]);
                unsigned long long aa;
                asm("mov.b64 %0, {%1, %1};" : "=l"(aa) : "r"(avu));
                asm("fma.rn.f32x2 %0, %1, %2, %0;" : "+l"(acc2[i][0]) : "l"(aa), "l"(bb0.x));
                asm("fma.rn.f32x2 %0, %1, %2, %0;" : "+l"(acc2[i][1]) : "l"(aa), "l"(bb0.y));
                asm("fma.rn.f32x2 %0, %1, %2, %0;" : "+l"(acc2[i][2]) : "l"(aa), "l"(bb1.x));
                asm("fma.rn.f32x2 %0, %1, %2, %0;" : "+l"(acc2[i][3]) : "l"(aa), "l"(bb1.y));
            }
        }
        __syncthreads();
    }

    int cA = bn + tcol * 4;
    int cB = bn + 64 + tcol * 4;
#pragma unroll
    for (int i = 0; i < 8; i++) {
        int r = bm + trow * 8 + i;
        if (r >= M) break;
        float v[8];
#pragma unroll
        for (int j = 0; j < 4; j++) {
            unsigned lo, hi;
            asm("mov.b64 {%0, %1}, %2;" : "=r"(lo), "=r"(hi) : "l"(acc2[i][j]));
            v[j * 2]     = __uint_as_float(lo);
            v[j * 2 + 1] = __uint_as_float(hi);
        }
        if (bias) {
#pragma unroll
            for (int j = 0; j < 4; j++) { v[j] += bias[cA + j]; v[4 + j] += bias[cB + j]; }
        }
        float4 s0 = make_float4(v[0], v[1], v[2], v[3]);
        float4 s1 = make_float4(v[4], v[5], v[6], v[7]);
        *reinterpret_cast<float4*>(C + (long long)r * N + cA) = s0;
        *reinterpret_cast<float4*>(C + (long long)r * N + cB) = s1;
        if (out2) {
            float sc = selfc[r];
            float4 o0, o1;
            o0.x = bias2[cA + 0] + v[0] * sc; o0.y = bias2[cA + 1] + v[1] * sc;
            o0.z = bias2[cA + 2] + v[2] * sc; o0.w = bias2[cA + 3] + v[3] * sc;
            o1.x = bias2[cB + 0] + v[4] * sc; o1.y = bias2[cB + 1] + v[5] * sc;
            o1.z = bias2[cB + 2] + v[6] * sc; o1.w = bias2[cB + 3] + v[7] * sc;
            *reinterpret_cast<float4*>(out2 + (long long)r * N + cA) = o0;
            *reinterpret_cast<float4*>(out2 + (long long)r * N + cB) = o1;
        }
    }
}

// -------- edge scatter: out[col] += norm * h[row] --------
__global__ void agg_edges_kernel(const float* __restrict__ h,
                                 const int* __restrict__ erow,
                                 const int* __restrict__ ecol,
                                 float* __restrict__ out) {
    long long gid = (long long)blockIdx.x * blockDim.x + threadIdx.x;
    int e = (int)(gid >> 7);
    int c4 = (int)(gid & 127);
    if (e >= EE) return;
    int r = erow[e];
    int c = ecol[e];
    float nm = g_norm[e];
    float4 v = *reinterpret_cast<const float4*>(h + (long long)r * HH + c4 * 4);
    float* dst = out + (long long)c * HH + c4 * 4;
    asm volatile("red.global.add.v4.f32 [%0], {%1, %2, %3, %4};"
                 :: "l"(dst), "f"(v.x * nm), "f"(v.y * nm), "f"(v.z * nm), "f"(v.w * nm)
                 : "memory");
}

// -------- batchnorm --------
__global__ void bn_stats_kernel(const float* __restrict__ X, float* __restrict__ sum,
                                float* __restrict__ sumsq) {
    int f = threadIdx.x;
    float s = 0.f, s2 = 0.f;
    for (int r = blockIdx.x; r < NN; r += gridDim.x) {
        float v = X[(long long)r * HH + f];
        s += v;
        s2 += v * v;
    }
    atomicAdd(&sum[f], s);
    atomicAdd(&sumsq[f], s2);
}

__global__ void bn_coef_kernel(const float* __restrict__ sum, const float* __restrict__ sumsq,
                               const float* __restrict__ g, const float* __restrict__ beta) {
    int f = threadIdx.x;
    float invN = 1.0f / (float)NN;
    float mu = sum[f] * invN;
    float var = fmaxf(sumsq[f] * invN - mu * mu, 0.0f);
    float s = g[f] * rsqrtf(var + EPS);
    g_bna[f] = s;
    g_bnc[f] = beta[f] - s * mu;
}

__global__ void bn_apply_kernel(const float* __restrict__ X, float* __restrict__ Y) {
    long long i4 = (long long)blockIdx.x * blockDim.x + threadIdx.x;
    long long base = i4 * 4;
    if (base >= (long long)NN * HH) return;
    int f = (int)(base & 511);
    float4 v = *reinterpret_cast<const float4*>(X + base);
    float4 a = *reinterpret_cast<const float4*>(g_bna + f);
    float4 c = *reinterpret_cast<const float4*>(g_bnc + f);
    float4 o;
    o.x = fmaf(a.x, v.x, c.x); o.y = fmaf(a.y, v.y, c.y);
    o.z = fmaf(a.z, v.z, c.z); o.w = fmaf(a.w, v.w, c.w);
    o.x = o.x > 0.f ? o.x : SLOPE * o.x;
    o.y = o.y > 0.f ? o.y : SLOPE * o.y;
    o.z = o.z > 0.f ? o.z : SLOPE * o.z;
    o.w = o.w > 0.f ? o.w : SLOPE * o.w;
    *reinterpret_cast<float4*>(Y + base) = o;
}

// -------- fused BN-apply + LeakyReLU + segment-max pool (layer 2) --------
__global__ void bn_pool_kernel(const float* __restrict__ X, const int* __restrict__ batch) {
    long long i4 = (long long)blockIdx.x * blockDim.x + threadIdx.x;
    long long base = i4 * 4;
    if (base >= (long long)NN * HH) return;
    int node = (int)(base >> 9);
    int f = (int)(base & 511);
    int grp = batch[node];
    float4 v = *reinterpret_cast<const float4*>(X + base);
    float4 a = *reinterpret_cast<const float4*>(g_bna + f);
    float4 c = *reinterpret_cast<const float4*>(g_bnc + f);
    float o[4];
    o[0] = fmaf(a.x, v.x, c.x); o[1] = fmaf(a.y, v.y, c.y);
    o[2] = fmaf(a.z, v.z, c.z); o[3] = fmaf(a.w, v.w, c.w);
    unsigned* dst = &g_keys[(long long)grp * HH + f];
#pragma unroll
    for (int j = 0; j < 4; j++) {
        float ov = o[j] > 0.f ? o[j] : SLOPE * o[j];
        unsigned u = __float_as_uint(ov);
        u = (u & 0x80000000u) ? ~u : (u | 0x80000000u);
        atomicMax(&dst[j], u);
    }
}

__global__ void pool_decode_kernel() {
    long long i = (long long)blockIdx.x * blockDim.x + threadIdx.x;
    if (i >= (long long)GG * HH) return;
    unsigned k = g_keys[i];
    float v;
    if (k == 0u) {
        v = 0.0f;
    } else {
        unsigned u = (k & 0x80000000u) ? (k & 0x7fffffffu) : ~k;
        v = __uint_as_float(u);
    }
    g_pooled[i] = v;
}

// -------- host launch --------
extern "C" void kernel_launch(void* const* d_in, const int* in_sizes, int n_in,
                              void* d_out, int out_size) {
    const float* x      = (const float*)d_in[0];
    const int*   ei     = (const int*)d_in[1];
    const int*   bt     = (const int*)d_in[2];
    const float* W1     = (const float*)d_in[3];
    const float* b1     = (const float*)d_in[4];
    const float* g1     = (const float*)d_in[5];
    const float* beta1  = (const float*)d_in[6];
    const float* W2     = (const float*)d_in[7];
    const float* b2     = (const float*)d_in[8];
    const float* g2     = (const float*)d_in[9];
    const float* beta2  = (const float*)d_in[10];
    const float* Wf     = (const float*)d_in[11];
    const float* bf     = (const float*)d_in[12];
    float* out = (float*)d_out;

    const int* erow = ei;
    const int* ecol = ei + EE;

    float *buf1, *buf2, *buf3, *pooled, *stats, *selfc;
    cudaGetSymbolAddress((void**)&buf1, g_buf1);
    cudaGetSymbolAddress((void**)&buf2, g_buf2);
    cudaGetSymbolAddress((void**)&buf3, g_buf3);
    cudaGetSymbolAddress((void**)&pooled, g_pooled);
    cudaGetSymbolAddress((void**)&stats, g_stats);
    cudaGetSymbolAddress((void**)&selfc, g_selfc);

    const int T = 256;
    init_kernel<<<(GG * HH + T - 1) / T, T>>>();
    count_deg_kernel<<<(EE + T - 1) / T, T>>>(ecol);
    dinv_kernel<<<(NN + T - 1) / T, T>>>();
    edge_norm_kernel<<<(EE + T - 1) / T, T>>>(erow, ecol);

    long long elems = (long long)NN * HH;
    int blk_elem4 = (int)((elems / 4 + T - 1) / T);
    int blk_edges = (int)(((long long)EE * 128 + T - 1) / T);

    // ---- layer 1: GEMM (h1 -> buf1, pre-agg b1+selfc*h1 -> buf2) ----
    {
        dim3 grid(HH / BN, (NN + BM - 1) / BM);
        sgemm_f32x2<<<grid, 256>>>(x, W1, nullptr, buf1, selfc, b1, buf2, NN, HH, DINF);
    }
    agg_edges_kernel<<<blk_edges, T>>>(buf1, erow, ecol, buf2);
    bn_stats_kernel<<<1024, HH>>>(buf2, stats + 0, stats + HH);
    bn_coef_kernel<<<1, HH>>>(stats + 0, stats + HH, g1, beta1);
    bn_apply_kernel<<<blk_elem4, T>>>(buf2, buf1);

    // ---- layer 2: GEMM (h2 -> buf2, pre-agg b2+selfc*h2 -> buf3) ----
    {
        dim3 grid(HH / BN, (NN + BM - 1) / BM);
        sgemm_f32x2<<<grid, 256>>>(buf1, W2, nullptr, buf2, selfc, b2, buf3, NN, HH, HH);
    }
    agg_edges_kernel<<<blk_edges, T>>>(buf2, erow, ecol, buf3);
    bn_stats_kernel<<<1024, HH>>>(buf3, stats + 2 * HH, stats + 3 * HH);
    bn_coef_kernel<<<1, HH>>>(stats + 2 * HH, stats + 3 * HH, g2, beta2);
    bn_pool_kernel<<<blk_elem4, T>>>(buf3, bt);

    // ---- pool decode + final linear ----
    pool_decode_kernel<<<(GG * HH + T - 1) / T, T>>>();
    {
        dim3 grid(OUTC / BN, (GG + BM - 1) / BM);
        sgemm_f32x2<<<grid, 256>>>(pooled, Wf, bf, out, nullptr, nullptr, nullptr, GG, OUTC, HH);
    }
}